// round 14
// baseline (speedup 1.0000x reference)
#include <cuda_runtime.h>
#include <cuda_fp16.h>
#include <math.h>

// GATNET: N=20000, E=640000, IN=256, H=4, OUT=64
#define NN   20000
#define EE   640000
#define ET   (EE + NN)
#define KIN  256
#define HC   256
#define H1   4
#define C1   64
#define C2   64

__device__ __half g_h1h[NN * HC];
__device__ float  g_x1[NN * HC];
__device__ __half g_h2h[NN * C2];
__device__ float  g_as1[NN * H1];
__device__ float  g_ad1[NN * H1];
__device__ float  g_as2[NN];
__device__ float  g_ad2[NN];
__device__ int    g_cnt[NN];
__device__ int    g_ptr[NN + 1];
__device__ int    g_cur[NN];
__device__ int    g_csr_src[ET];
__device__ float  g_w1c[ET * H1];
__device__ float  g_w2c[ET];
__device__ int    g_is64;

// ---------------- fast exp on the FMA pipe (no MUFU, no libm routine) ----------------
// exp(x) = 2^n * exp(t), n = rint(x*log2e), t = x - n*ln2, |t| <= 0.347
// degree-4 Taylor: rel err <= 4e-5 (negligible for softmax weights)
__device__ __forceinline__ float fexp(float x) {
    float y = x * 1.4426950408889634f;
    float n = rintf(y);
    float t = fmaf(-n, 0.6931471805599453f, x);
    float p = fmaf(t, 0.041666667f, 0.166666667f);
    p = fmaf(t, p, 0.5f);
    p = fmaf(t, p, 1.0f);
    p = fmaf(t, p, 1.0f);
    int e = (((int)n) + 127) << 23;
    return p * __int_as_float(e);
}

// ---------------- dtype probe + zero counts (fused) ----------------
__global__ void detect_zero_k(const long long* __restrict__ ei64) {
    int t = blockIdx.x * blockDim.x + threadIdx.x;
    if (t < NN) g_cnt[t] = 0;
    if (blockIdx.x == 0) {
        __shared__ int bad;
        if (threadIdx.x == 0) bad = 0;
        __syncthreads();
        for (int i = threadIdx.x; i < 2048; i += blockDim.x) {
            long long v = ei64[i];
            if (v < 0 || v >= NN) bad = 1;
        }
        __syncthreads();
        if (threadIdx.x == 0) g_is64 = bad ? 0 : 1;
    }
}

__device__ __forceinline__ void load_edge(const void* __restrict__ ei, int e, int& s, int& d) {
    if (e >= EE) { s = d = e - EE; return; }
    if (g_is64) {
        const long long* p = (const long long*)ei;
        s = (int)p[e]; d = (int)p[EE + e];
    } else {
        const int* p = (const int*)ei;
        s = p[e]; d = p[EE + e];
    }
}

__global__ void count_k(const void* __restrict__ ei) {
    int e = blockIdx.x * blockDim.x + threadIdx.x;
    if (e >= ET) return;
    int d;
    if (e >= EE) d = e - EE;
    else if (g_is64) d = (int)((const long long*)ei)[EE + e];
    else             d = ((const int*)ei)[EE + e];
    if ((unsigned)d < NN) atomicAdd(&g_cnt[d], 1);
}

// ---------------- fast single-block scan ----------------
__global__ __launch_bounds__(1024) void scan_fast_k() {
    const int T = 20;
    int tid = threadIdx.x;
    int base = tid * T;
    int pre[T];
    int s = 0;
#pragma unroll
    for (int i = 0; i < T; i++) {
        int idx = base + i;
        int v = (idx < NN) ? g_cnt[idx] : 0;
        pre[i] = s; s += v;
    }
    int lane = tid & 31, wid = tid >> 5;
    int incl = s;
#pragma unroll
    for (int o = 1; o < 32; o <<= 1) {
        int n = __shfl_up_sync(0xffffffffu, incl, o);
        if (lane >= o) incl += n;
    }
    __shared__ int wsum[32];
    if (lane == 31) wsum[wid] = incl;
    __syncthreads();
    if (wid == 0) {
        int v = wsum[lane];
        int wi = v;
#pragma unroll
        for (int o = 1; o < 32; o <<= 1) {
            int n = __shfl_up_sync(0xffffffffu, wi, o);
            if (lane >= o) wi += n;
        }
        wsum[lane] = wi - v;
    }
    __syncthreads();
    int off = wsum[wid] + incl - s;
#pragma unroll
    for (int i = 0; i < T; i++) {
        int idx = base + i;
        if (idx < NN) { int p = off + pre[i]; g_ptr[idx] = p; g_cur[idx] = p; }
    }
    if (tid == 1023) g_ptr[NN] = off + s;
}

__global__ void scatter_k(const void* __restrict__ ei) {
    int e = blockIdx.x * blockDim.x + threadIdx.x;
    if (e >= ET) return;
    int s, d; load_edge(ei, e, s, d);
    if ((unsigned)d < NN && (unsigned)s < NN) {
        int pos = atomicAdd(&g_cur[d], 1);
        g_csr_src[pos] = s;
    }
}

// ---------------- SGEMM 64x64 + fused attention-logit epilogue ----------------
__global__ __launch_bounds__(256) void sgemm_fused_k(const float* __restrict__ A,
                                                     const float* __restrict__ B,
                                                     __half* __restrict__ Ch,
                                                     const float* __restrict__ attS,
                                                     const float* __restrict__ attD,
                                                     float* __restrict__ asOut,
                                                     float* __restrict__ adOut,
                                                     int HS,
                                                     int M, int N, int K) {
    __shared__ float As[16][68];
    __shared__ float Bs[16][64];
    const int bn = blockIdx.x * 64;
    const int bm = blockIdx.y * 64;
    const int tid = threadIdx.x;
    const int tx = tid & 15, ty = tid >> 4;
    const int la_k = tid & 15, la_m = tid >> 4;
    const int lb_c = tid & 63, lb_k = tid >> 6;
    float acc[4][4] = {};

    for (int k0 = 0; k0 < K; k0 += 16) {
#pragma unroll
        for (int i = 0; i < 4; i++) {
            int m = la_m + i * 16;
            int gm = bm + m;
            As[la_k][m] = (gm < M) ? A[(size_t)gm * K + k0 + la_k] : 0.0f;
        }
#pragma unroll
        for (int i = 0; i < 4; i++) {
            int kk = lb_k + i * 4;
            Bs[kk][lb_c] = B[(size_t)(k0 + kk) * N + bn + lb_c];
        }
        __syncthreads();
#pragma unroll
        for (int k = 0; k < 16; k++) {
            float4 a4 = *(const float4*)&As[k][ty * 4];
            float4 b4 = *(const float4*)&Bs[k][tx * 4];
            float av[4] = {a4.x, a4.y, a4.z, a4.w};
            float bv[4] = {b4.x, b4.y, b4.z, b4.w};
#pragma unroll
            for (int i = 0; i < 4; i++)
#pragma unroll
                for (int j = 0; j < 4; j++) acc[i][j] += av[i] * bv[j];
        }
        __syncthreads();
    }

    float asv[4], adv[4];
#pragma unroll
    for (int j = 0; j < 4; j++) {
        asv[j] = attS[bn + tx * 4 + j];
        adv[j] = attD[bn + tx * 4 + j];
    }
    const int h = blockIdx.x;

#pragma unroll
    for (int i = 0; i < 4; i++) {
        int gm = bm + ty * 4 + i;
        float s = acc[i][0] * asv[0] + acc[i][1] * asv[1] + acc[i][2] * asv[2] + acc[i][3] * asv[3];
        float d = acc[i][0] * adv[0] + acc[i][1] * adv[1] + acc[i][2] * adv[2] + acc[i][3] * adv[3];
#pragma unroll
        for (int o = 8; o; o >>= 1) {
            s += __shfl_down_sync(0xffffffffu, s, o, 16);
            d += __shfl_down_sync(0xffffffffu, d, o, 16);
        }
        if (gm < M) {
            if (tx == 0) {
                asOut[(size_t)gm * HS + h] = s;
                adOut[(size_t)gm * HS + h] = d;
            }
            __half2* hp = (__half2*)&Ch[(size_t)gm * N + bn + tx * 4];
            hp[0] = __floats2half2_rn(acc[i][0], acc[i][1]);
            hp[1] = __floats2half2_rn(acc[i][2], acc[i][3]);
        }
    }
}

// ---------------- fused edge-softmax + fp16 gather, layer 1 ----------------
__global__ __launch_bounds__(256) void gat1_k(const float* __restrict__ bias1) {
    const int d = blockIdx.x;
    const int tid = threadIdx.x;
    const int p0 = g_ptr[d], p1 = g_ptr[d + 1];
    const int cnt = p1 - p0;

    float loc[H1] = {0.f, 0.f, 0.f, 0.f};
    const int items = cnt * H1;
    for (int i = tid; i < items; i += 256) {
        int j = p0 + (i >> 2);
        int h = i & 3;
        int s = g_csr_src[j];
        float x = g_as1[s * H1 + h] + g_ad1[d * H1 + h];
        x = (x > 0.f) ? x : 0.2f * x;
        x = fmaxf(x, -60.f);
        float w = fexp(x);
        g_w1c[j * H1 + h] = w;
        loc[h] += w;
    }
#pragma unroll
    for (int h = 0; h < H1; h++)
#pragma unroll
        for (int o = 16; o; o >>= 1) loc[h] += __shfl_down_sync(0xffffffffu, loc[h], o);
    __shared__ float sw[8][H1];
    if ((tid & 31) == 0)
#pragma unroll
        for (int h = 0; h < H1; h++) sw[tid >> 5][h] = loc[h];
    __syncthreads();
    __shared__ float sinv[H1];
    if (tid < H1) {
        float s = 0.f;
#pragma unroll
        for (int w = 0; w < 8; w++) s += sw[w][tid];
        sinv[tid] = 1.0f / (s + 1e-16f);
    }
    __syncthreads();

    const int eo = tid >> 7;
    const int fi = tid & 127;
    const int f  = fi * 2;
    const int h  = f >> 6;
    const float inv = sinv[h];
    float2 acc = make_float2(0.f, 0.f);
    const __half2* h1h = (const __half2*)g_h1h;
    for (int j = p0 + eo; j < p1; j += 2) {
        int s = g_csr_src[j];
        float w = g_w1c[j * H1 + h];
        float2 v = __half22float2(h1h[(size_t)s * (HC / 2) + fi]);
        acc.x += w * v.x;
        acc.y += w * v.y;
    }
    __shared__ float2 part[128];
    if (eo == 1) part[fi] = acc;
    __syncthreads();
    if (eo == 0) {
        acc.x += part[fi].x;
        acc.y += part[fi].y;
        float v0 = acc.x * inv + bias1[f];
        float v1 = acc.y * inv + bias1[f + 1];
        v0 = (v0 > 0.f) ? v0 : expm1f(v0);
        v1 = (v1 > 0.f) ? v1 : expm1f(v1);
        g_x1[(size_t)d * HC + f]     = v0;
        g_x1[(size_t)d * HC + f + 1] = v1;
    }
}

// ---------------- fused edge-softmax + fp16 gather, layer 2 ----------------
__global__ __launch_bounds__(64) void gat2_k(const float* __restrict__ bias2,
                                             float* __restrict__ out) {
    const int d = blockIdx.x;
    const int tid = threadIdx.x;
    const int p0 = g_ptr[d], p1 = g_ptr[d + 1];
    const int cnt = p1 - p0;

    float loc = 0.f;
    const float ad = g_ad2[d];
    for (int i = tid; i < cnt; i += 64) {
        int j = p0 + i;
        int s = g_csr_src[j];
        float x = g_as2[s] + ad;
        x = (x > 0.f) ? x : 0.2f * x;
        x = fmaxf(x, -60.f);
        float w = fexp(x);
        g_w2c[j] = w;
        loc += w;
    }
#pragma unroll
    for (int o = 16; o; o >>= 1) loc += __shfl_down_sync(0xffffffffu, loc, o);
    __shared__ float sw2[2];
    if ((tid & 31) == 0) sw2[tid >> 5] = loc;
    __syncthreads();
    __shared__ float sinv2;
    if (tid == 0) sinv2 = 1.0f / (sw2[0] + sw2[1] + 1e-16f);
    __syncthreads();

    const int eo = tid >> 5;
    const int fi = tid & 31;
    const int f  = fi * 2;
    const float inv = sinv2;
    float2 acc = make_float2(0.f, 0.f);
    const __half2* h2h = (const __half2*)g_h2h;
    for (int j = p0 + eo; j < p1; j += 2) {
        int s = g_csr_src[j];
        float w = g_w2c[j];
        float2 v = __half22float2(h2h[(size_t)s * (C2 / 2) + fi]);
        acc.x += w * v.x;
        acc.y += w * v.y;
    }
    __shared__ float2 part2[32];
    if (eo == 1) part2[fi] = acc;
    __syncthreads();
    if (eo == 0) {
        acc.x += part2[fi].x;
        acc.y += part2[fi].y;
        out[(size_t)d * C2 + f]     = acc.x * inv + bias2[f];
        out[(size_t)d * C2 + f + 1] = acc.y * inv + bias2[f + 1];
    }
}

// ---------------- launch ----------------
extern "C" void kernel_launch(void* const* d_in, const int* in_sizes, int n_in,
                              void* d_out, int out_size) {
    const float* x   = (const float*)d_in[0];
    const void*  ei  = d_in[1];
    const float* W1  = (const float*)d_in[2];
    const float* as1 = (const float*)d_in[3];
    const float* ad1 = (const float*)d_in[4];
    const float* b1  = (const float*)d_in[5];
    const float* W2  = (const float*)d_in[6];
    const float* as2 = (const float*)d_in[7];
    const float* ad2 = (const float*)d_in[8];
    const float* b2  = (const float*)d_in[9];
    float* out = (float*)d_out;

    // R7 root cause: resolve true device addresses of __device__ symbols
    // used as kernel args (host-shadow writes are silently absorbed via ATS).
    __half *h1hp = nullptr, *h2hp = nullptr;
    float  *x1p = nullptr, *as1p = nullptr, *ad1p = nullptr, *as2p = nullptr, *ad2p = nullptr;
    cudaGetSymbolAddress((void**)&h1hp, g_h1h);
    cudaGetSymbolAddress((void**)&h2hp, g_h2h);
    cudaGetSymbolAddress((void**)&x1p,  g_x1);
    cudaGetSymbolAddress((void**)&as1p, g_as1);
    cudaGetSymbolAddress((void**)&ad1p, g_ad1);
    cudaGetSymbolAddress((void**)&as2p, g_as2);
    cudaGetSymbolAddress((void**)&ad2p, g_ad2);

    detect_zero_k<<<(NN + 255) / 256, 256>>>((const long long*)ei);
    count_k<<<(ET + 255) / 256, 256>>>(ei);
    scan_fast_k<<<1, 1024>>>();
    scatter_k<<<(ET + 255) / 256, 256>>>(ei);

    // layer 1: h1 = x @ W1 (fp16 out) + fused att1 logits
    { dim3 g(HC / 64, (NN + 63) / 64);
      sgemm_fused_k<<<g, 256>>>(x, W1, h1hp, as1, ad1, as1p, ad1p, H1, NN, HC, KIN); }
    gat1_k<<<NN, 256>>>(b1);

    // layer 2: h2 = x1 @ W2 (fp16 out) + fused att2 logits
    { dim3 g(C2 / 64, (NN + 63) / 64);
      sgemm_fused_k<<<g, 256>>>(x1p, W2, h2hp, as2, ad2, as2p, ad2p, 1, NN, C2, HC); }
    gat2_k<<<NN, 64>>>(b2, out);
}

// round 15
// speedup vs baseline: 1.3216x; 1.3216x over previous
#include <cuda_runtime.h>
#include <cuda_fp16.h>
#include <mma.h>
#include <math.h>

using namespace nvcuda;

// GATNET: N=20000, E=640000, IN=256, H=4, OUT=64
#define NN   20000
#define EE   640000
#define ET   (EE + NN)
#define KIN  256
#define HC   256
#define H1   4
#define C1   64
#define C2   64

__device__ __half g_xh[NN * KIN];    // fp16 x
__device__ __half g_w1h[KIN * HC];   // fp16 W1
__device__ __half g_w2h[HC * C2];    // fp16 W2
__device__ __half g_h1h[NN * HC];
__device__ __half g_x1h[NN * HC];    // fp16 x1 (layer-2 GEMM input)
__device__ __half g_h2h[NN * C2];
__device__ float  g_as1[NN * H1];
__device__ float  g_ad1[NN * H1];
__device__ float  g_as2[NN];
__device__ float  g_ad2[NN];
__device__ int    g_cnt[NN];
__device__ int    g_ptr[NN + 1];
__device__ int    g_cur[NN];
__device__ int    g_csr_src[ET];
__device__ float  g_w1c[ET * H1];
__device__ float  g_w2c[ET];
__device__ int    g_is64;

// ---------------- fast exp (FMA pipe only) ----------------
__device__ __forceinline__ float fexp(float x) {
    float y = x * 1.4426950408889634f;
    float n = rintf(y);
    float t = fmaf(-n, 0.6931471805599453f, x);
    float p = fmaf(t, 0.041666667f, 0.166666667f);
    p = fmaf(t, p, 0.5f);
    p = fmaf(t, p, 1.0f);
    p = fmaf(t, p, 1.0f);
    int e = (((int)n) + 127) << 23;
    return p * __int_as_float(e);
}

// ---------------- fp32 -> fp16 conversion (n multiple of 4) ----------------
__global__ void f2h_k(const float* __restrict__ src, __half* __restrict__ dst, int n4) {
    int i = blockIdx.x * blockDim.x + threadIdx.x;
    if (i >= n4) return;
    float4 v = ((const float4*)src)[i];
    __half2* d = (__half2*)dst + i * 2;
    d[0] = __floats2half2_rn(v.x, v.y);
    d[1] = __floats2half2_rn(v.z, v.w);
}

// ---------------- dtype probe + zero counts (fused) ----------------
__global__ void detect_zero_k(const long long* __restrict__ ei64) {
    int t = blockIdx.x * blockDim.x + threadIdx.x;
    if (t < NN) g_cnt[t] = 0;
    if (blockIdx.x == 0) {
        __shared__ int bad;
        if (threadIdx.x == 0) bad = 0;
        __syncthreads();
        for (int i = threadIdx.x; i < 2048; i += blockDim.x) {
            long long v = ei64[i];
            if (v < 0 || v >= NN) bad = 1;
        }
        __syncthreads();
        if (threadIdx.x == 0) g_is64 = bad ? 0 : 1;
    }
}

__device__ __forceinline__ void load_edge(const void* __restrict__ ei, int e, int& s, int& d) {
    if (e >= EE) { s = d = e - EE; return; }
    if (g_is64) {
        const long long* p = (const long long*)ei;
        s = (int)p[e]; d = (int)p[EE + e];
    } else {
        const int* p = (const int*)ei;
        s = p[e]; d = p[EE + e];
    }
}

__global__ void count_k(const void* __restrict__ ei) {
    int e = blockIdx.x * blockDim.x + threadIdx.x;
    if (e >= ET) return;
    int d;
    if (e >= EE) d = e - EE;
    else if (g_is64) d = (int)((const long long*)ei)[EE + e];
    else             d = ((const int*)ei)[EE + e];
    if ((unsigned)d < NN) atomicAdd(&g_cnt[d], 1);
}

// ---------------- fast single-block scan ----------------
__global__ __launch_bounds__(1024) void scan_fast_k() {
    const int T = 20;
    int tid = threadIdx.x;
    int base = tid * T;
    int pre[T];
    int s = 0;
#pragma unroll
    for (int i = 0; i < T; i++) {
        int idx = base + i;
        int v = (idx < NN) ? g_cnt[idx] : 0;
        pre[i] = s; s += v;
    }
    int lane = tid & 31, wid = tid >> 5;
    int incl = s;
#pragma unroll
    for (int o = 1; o < 32; o <<= 1) {
        int n = __shfl_up_sync(0xffffffffu, incl, o);
        if (lane >= o) incl += n;
    }
    __shared__ int wsum[32];
    if (lane == 31) wsum[wid] = incl;
    __syncthreads();
    if (wid == 0) {
        int v = wsum[lane];
        int wi = v;
#pragma unroll
        for (int o = 1; o < 32; o <<= 1) {
            int n = __shfl_up_sync(0xffffffffu, wi, o);
            if (lane >= o) wi += n;
        }
        wsum[lane] = wi - v;
    }
    __syncthreads();
    int off = wsum[wid] + incl - s;
#pragma unroll
    for (int i = 0; i < T; i++) {
        int idx = base + i;
        if (idx < NN) { int p = off + pre[i]; g_ptr[idx] = p; g_cur[idx] = p; }
    }
    if (tid == 1023) g_ptr[NN] = off + s;
}

__global__ void scatter_k(const void* __restrict__ ei) {
    int e = blockIdx.x * blockDim.x + threadIdx.x;
    if (e >= ET) return;
    int s, d; load_edge(ei, e, s, d);
    if ((unsigned)d < NN && (unsigned)s < NN) {
        int pos = atomicAdd(&g_cur[d], 1);
        g_csr_src[pos] = s;
    }
}

// ---------------- fp16 WMMA GEMM 64x64 (BK=32) + fused logits epilogue ----------------
#define BK32 32
__global__ __launch_bounds__(256) void hgemm_fused_k(const __half* __restrict__ A,
                                                     const __half* __restrict__ B,
                                                     __half* __restrict__ Ch,
                                                     const float* __restrict__ attS,
                                                     const float* __restrict__ attD,
                                                     float* __restrict__ asOut,
                                                     float* __restrict__ adOut,
                                                     int HS,
                                                     int M, int N, int K) {
    __shared__ __half Ah[64][48];    // 6 KB   (stride 48 halves = 96 B, 16B-aligned)
    __shared__ __half Bh[32][80];    // 5 KB   (stride 80 halves = 160 B, 16B-aligned)
    __shared__ float  Cs[64][68];    // 17.4 KB epilogue staging
    const int bn = blockIdx.x * 64;
    const int bm = blockIdx.y * 64;
    const int tid = threadIdx.x;
    const int w = tid >> 5;
    const int wm = (w >> 1) * 16;
    const int wn = (w & 1) * 32;

    wmma::fragment<wmma::accumulator, 16, 16, 16, float> c0, c1;
    wmma::fill_fragment(c0, 0.f);
    wmma::fill_fragment(c1, 0.f);

    for (int k0 = 0; k0 < K; k0 += BK32) {
        // A: 64x32 halves, 1 float4 (8 halves) per thread
        {
            int row = tid >> 2, col8 = (tid & 3) * 8;
            int gm = bm + row;
            float4 v = make_float4(0.f, 0.f, 0.f, 0.f);
            if (gm < M) v = *(const float4*)&A[(size_t)gm * K + k0 + col8];
            *(float4*)&Ah[row][col8] = v;
        }
        // B: 32x64 halves, 1 float4 per thread
        {
            int row = tid >> 3, col8 = (tid & 7) * 8;
            *(float4*)&Bh[row][col8] = *(const float4*)&B[(size_t)(k0 + row) * N + bn + col8];
        }
        __syncthreads();
        wmma::fragment<wmma::matrix_a, 16, 16, 16, __half, wmma::row_major> af;
        wmma::fragment<wmma::matrix_b, 16, 16, 16, __half, wmma::row_major> b0, b1;
#pragma unroll
        for (int kk = 0; kk < BK32; kk += 16) {
            wmma::load_matrix_sync(af, &Ah[wm][kk], 48);
            wmma::load_matrix_sync(b0, &Bh[kk][wn], 80);
            wmma::load_matrix_sync(b1, &Bh[kk][wn + 16], 80);
            wmma::mma_sync(c0, af, b0, c0);
            wmma::mma_sync(c1, af, b1, c1);
        }
        __syncthreads();
    }

    wmma::store_matrix_sync(&Cs[wm][wn],      c0, 68, wmma::mem_row_major);
    wmma::store_matrix_sync(&Cs[wm][wn + 16], c1, 68, wmma::mem_row_major);
    __syncthreads();

    // epilogue (same as R13): logits + fp16 store
    const int tx = tid & 15, ty = tid >> 4;
    float asv[4], adv[4];
#pragma unroll
    for (int j = 0; j < 4; j++) {
        asv[j] = attS[bn + tx * 4 + j];
        adv[j] = attD[bn + tx * 4 + j];
    }
    const int h = blockIdx.x;
#pragma unroll
    for (int i = 0; i < 4; i++) {
        int gm = bm + ty * 4 + i;
        float a0 = Cs[ty * 4 + i][tx * 4 + 0];
        float a1 = Cs[ty * 4 + i][tx * 4 + 1];
        float a2 = Cs[ty * 4 + i][tx * 4 + 2];
        float a3 = Cs[ty * 4 + i][tx * 4 + 3];
        float s = a0 * asv[0] + a1 * asv[1] + a2 * asv[2] + a3 * asv[3];
        float d = a0 * adv[0] + a1 * adv[1] + a2 * adv[2] + a3 * adv[3];
#pragma unroll
        for (int o = 8; o; o >>= 1) {
            s += __shfl_down_sync(0xffffffffu, s, o, 16);
            d += __shfl_down_sync(0xffffffffu, d, o, 16);
        }
        if (gm < M) {
            if (tx == 0) {
                asOut[(size_t)gm * HS + h] = s;
                adOut[(size_t)gm * HS + h] = d;
            }
            __half2* hp = (__half2*)&Ch[(size_t)gm * N + bn + tx * 4];
            hp[0] = __floats2half2_rn(a0, a1);
            hp[1] = __floats2half2_rn(a2, a3);
        }
    }
}

// ---------------- fused edge-softmax + fp16 gather, layer 1 ----------------
__global__ __launch_bounds__(256) void gat1_k(const float* __restrict__ bias1) {
    const int d = blockIdx.x;
    const int tid = threadIdx.x;
    const int p0 = g_ptr[d], p1 = g_ptr[d + 1];
    const int cnt = p1 - p0;

    float loc[H1] = {0.f, 0.f, 0.f, 0.f};
    const int items = cnt * H1;
    for (int i = tid; i < items; i += 256) {
        int j = p0 + (i >> 2);
        int h = i & 3;
        int s = g_csr_src[j];
        float x = g_as1[s * H1 + h] + g_ad1[d * H1 + h];
        x = (x > 0.f) ? x : 0.2f * x;
        x = fmaxf(x, -60.f);
        float w = fexp(x);
        g_w1c[j * H1 + h] = w;
        loc[h] += w;
    }
#pragma unroll
    for (int h = 0; h < H1; h++)
#pragma unroll
        for (int o = 16; o; o >>= 1) loc[h] += __shfl_down_sync(0xffffffffu, loc[h], o);
    __shared__ float sw[8][H1];
    if ((tid & 31) == 0)
#pragma unroll
        for (int h = 0; h < H1; h++) sw[tid >> 5][h] = loc[h];
    __syncthreads();
    __shared__ float sinv[H1];
    if (tid < H1) {
        float s = 0.f;
#pragma unroll
        for (int w = 0; w < 8; w++) s += sw[w][tid];
        sinv[tid] = 1.0f / (s + 1e-16f);
    }
    __syncthreads();

    const int eo = tid >> 7;
    const int fi = tid & 127;
    const int f  = fi * 2;
    const int h  = f >> 6;
    const float inv = sinv[h];
    float2 acc = make_float2(0.f, 0.f);
    const __half2* h1h = (const __half2*)g_h1h;
#pragma unroll 4
    for (int j = p0 + eo; j < p1; j += 2) {
        int s = g_csr_src[j];
        float w = g_w1c[j * H1 + h];
        float2 v = __half22float2(h1h[(size_t)s * (HC / 2) + fi]);
        acc.x += w * v.x;
        acc.y += w * v.y;
    }
    __shared__ float2 part[128];
    if (eo == 1) part[fi] = acc;
    __syncthreads();
    if (eo == 0) {
        acc.x += part[fi].x;
        acc.y += part[fi].y;
        float v0 = acc.x * inv + bias1[f];
        float v1 = acc.y * inv + bias1[f + 1];
        v0 = (v0 > 0.f) ? v0 : expm1f(v0);
        v1 = (v1 > 0.f) ? v1 : expm1f(v1);
        ((__half2*)g_x1h)[(size_t)d * (HC / 2) + fi] = __floats2half2_rn(v0, v1);  // fp16 x1
    }
}

// ---------------- fused edge-softmax + fp16 gather, layer 2 ----------------
__global__ __launch_bounds__(64) void gat2_k(const float* __restrict__ bias2,
                                             float* __restrict__ out) {
    const int d = blockIdx.x;
    const int tid = threadIdx.x;
    const int p0 = g_ptr[d], p1 = g_ptr[d + 1];
    const int cnt = p1 - p0;

    float loc = 0.f;
    const float ad = g_ad2[d];
    for (int i = tid; i < cnt; i += 64) {
        int j = p0 + i;
        int s = g_csr_src[j];
        float x = g_as2[s] + ad;
        x = (x > 0.f) ? x : 0.2f * x;
        x = fmaxf(x, -60.f);
        float w = fexp(x);
        g_w2c[j] = w;
        loc += w;
    }
#pragma unroll
    for (int o = 16; o; o >>= 1) loc += __shfl_down_sync(0xffffffffu, loc, o);
    __shared__ float sw2[2];
    if ((tid & 31) == 0) sw2[tid >> 5] = loc;
    __syncthreads();
    __shared__ float sinv2;
    if (tid == 0) sinv2 = 1.0f / (sw2[0] + sw2[1] + 1e-16f);
    __syncthreads();

    const int eo = tid >> 5;
    const int fi = tid & 31;
    const int f  = fi * 2;
    const float inv = sinv2;
    float2 acc = make_float2(0.f, 0.f);
    const __half2* h2h = (const __half2*)g_h2h;
#pragma unroll 4
    for (int j = p0 + eo; j < p1; j += 2) {
        int s = g_csr_src[j];
        float w = g_w2c[j];
        float2 v = __half22float2(h2h[(size_t)s * (C2 / 2) + fi]);
        acc.x += w * v.x;
        acc.y += w * v.y;
    }
    __shared__ float2 part2[32];
    if (eo == 1) part2[fi] = acc;
    __syncthreads();
    if (eo == 0) {
        acc.x += part2[fi].x;
        acc.y += part2[fi].y;
        out[(size_t)d * C2 + f]     = acc.x * inv + bias2[f];
        out[(size_t)d * C2 + f + 1] = acc.y * inv + bias2[f + 1];
    }
}

// ---------------- launch ----------------
extern "C" void kernel_launch(void* const* d_in, const int* in_sizes, int n_in,
                              void* d_out, int out_size) {
    const float* x   = (const float*)d_in[0];
    const void*  ei  = d_in[1];
    const float* W1  = (const float*)d_in[2];
    const float* as1 = (const float*)d_in[3];
    const float* ad1 = (const float*)d_in[4];
    const float* b1  = (const float*)d_in[5];
    const float* W2  = (const float*)d_in[6];
    const float* as2 = (const float*)d_in[7];
    const float* ad2 = (const float*)d_in[8];
    const float* b2  = (const float*)d_in[9];
    float* out = (float*)d_out;

    // R7 root cause: resolve true device addresses of __device__ symbols
    // used as kernel args (host-shadow writes are silently absorbed via ATS).
    __half *xhp, *w1hp, *w2hp, *h1hp, *x1hp, *h2hp;
    float  *as1p, *ad1p, *as2p, *ad2p;
    cudaGetSymbolAddress((void**)&xhp,  g_xh);
    cudaGetSymbolAddress((void**)&w1hp, g_w1h);
    cudaGetSymbolAddress((void**)&w2hp, g_w2h);
    cudaGetSymbolAddress((void**)&h1hp, g_h1h);
    cudaGetSymbolAddress((void**)&x1hp, g_x1h);
    cudaGetSymbolAddress((void**)&h2hp, g_h2h);
    cudaGetSymbolAddress((void**)&as1p, g_as1);
    cudaGetSymbolAddress((void**)&ad1p, g_ad1);
    cudaGetSymbolAddress((void**)&as2p, g_as2);
    cudaGetSymbolAddress((void**)&ad2p, g_ad2);

    detect_zero_k<<<(NN + 255) / 256, 256>>>((const long long*)ei);
    count_k<<<(ET + 255) / 256, 256>>>(ei);
    scan_fast_k<<<1, 1024>>>();
    scatter_k<<<(ET + 255) / 256, 256>>>(ei);

    // one-time fp16 conversions
    f2h_k<<<(NN * KIN / 4 + 255) / 256, 256>>>(x, xhp, NN * KIN / 4);
    f2h_k<<<(KIN * HC / 4 + 255) / 256, 256>>>(W1, w1hp, KIN * HC / 4);
    f2h_k<<<(HC * C2 / 4 + 255) / 256, 256>>>(W2, w2hp, HC * C2 / 4);

    // layer 1: h1 = x @ W1 (fp16 tensor cores) + fused att1 logits
    { dim3 g(HC / 64, (NN + 63) / 64);
      hgemm_fused_k<<<g, 256>>>(xhp, w1hp, h1hp, as1, ad1, as1p, ad1p, H1, NN, HC, KIN); }
    gat1_k<<<NN, 256>>>(b1);

    // layer 2: h2 = x1 @ W2 (fp16 tensor cores) + fused att2 logits
    { dim3 g(C2 / 64, (NN + 63) / 64);
      hgemm_fused_k<<<g, 256>>>(x1hp, w2hp, h2hp, as2, ad2, as2p, ad2p, 1, NN, C2, HC); }
    gat2_k<<<NN, 64>>>(b2, out);
}